// round 16
// baseline (speedup 1.0000x reference)
#include <cuda_runtime.h>
#include <cstdint>

// OptimizedUniformSampler R16:
// - fast path isolated in its own kernel (generic bisect moved to a repair
//   kernel that early-exits when the fast path is valid) -> ncu attribution
// - blocked Bloom filter, k=2 bits in ONE 32-bit word (same 1 scattered load,
//   FP rate ~0.2% -> warp-divergent exact-scan almost never taken)
// - bucket_lo table (stale-tolerant) only for Bloom positives.
// Output float32: neg [3T] then keep [T].

#define THREADS 256
#define EPT 8
#define NB_BITS 19
#define NB (1 << NB_BITS)
#define BLOOM_WORDS (1 << 21)                 // 8 MB, zero-init at module load

__device__ int g_bad;                         // monotone validity flag
__device__ unsigned int g_bucket_lo[NB];      // 2 MB; never cleared (stale-tolerant)
__device__ unsigned int g_bloom[BLOOM_WORDS]; // idempotent build, no clear needed

static __device__ __forceinline__ unsigned int bucket_of64(long long h) {
    return ((unsigned int)(((unsigned long long)h >> 42) << 2)
          | (unsigned int)(((unsigned long long)h >> 29) & 3ULL)) & (NB - 1);
}

// blocked bloom: word index + 2 bit positions from one 64-bit product
static __device__ __forceinline__ void bloom_wm(long long h,
                                                unsigned int& w, unsigned int& m) {
    unsigned long long p = (unsigned long long)h * 0x9E3779B97F4A7C15ULL;
    w = (unsigned int)(p >> 43);                       // 21 bits
    unsigned int b1 = (unsigned int)(p >> 38) & 31u;
    unsigned int b2 = (unsigned int)(p >> 33) & 31u;
    m = (1u << b1) | (1u << b2);
}

// warp-collective width detection: 8 (int64) or 4 (int32)
static __device__ __forceinline__ int detect_width(const void* posv, int n_elems) {
    const unsigned int* pw = (const unsigned int*)posv;
    int lid = threadIdx.x & 31;
    int lim = n_elems < 64 ? n_elems : 64;
    unsigned int v = 0;
    int w = 2 * lid + 1;
    if (w < lim) v = __ldg(&pw[w]);
    unsigned int any = __ballot_sync(0xFFFFFFFFu, v != 0u);
    return any ? 4 : 8;
}

__global__ void build_kernel(const long long* __restrict__ hs, int L,
                             const void* __restrict__ posv, int pos_elems) {
    if (detect_width(posv, pos_elems) != 8) return;
    int i = blockIdx.x * blockDim.x + threadIdx.x;
    for (; i < L; i += gridDim.x * blockDim.x) {
        long long h = __ldg(&hs[i]);
        if (((unsigned long long)h >> 59) != 0ULL ||
            (((unsigned long long)h >> 31) & 0x7FFULL) != 0ULL)
            g_bad = 1;
        unsigned int w, m; bloom_wm(h, w, m);
        atomicOr(&g_bloom[w], m);                       // idempotent
        unsigned int b = bucket_of64(h);
        bool first = (i == 0) || (bucket_of64(__ldg(&hs[i - 1])) != b);
        if (first) g_bucket_lo[b] = (unsigned int)i;
    }
}

static __device__ __forceinline__ bool exact_member(
        const long long* __restrict__ hs, int L, long long h, unsigned int bkt) {
    unsigned int s = __ldg(&g_bucket_lo[bkt]);
    if (s >= (unsigned int)L) return false;
    int idx = (int)s;
    long long v = __ldg(&hs[idx]);
    if (bucket_of64(v) != bkt) return false;            // stale-entry rejection
    for (;;) {
        if (v >= h) return (v == h);
        if (++idx >= L) return false;
        v = __ldg(&hs[idx]);
    }
}

// ===================== FAST KERNEL (only fast path) =====================
__global__ __launch_bounds__(THREADS)
void fast_kernel(const void* __restrict__ posv,
                 const void* __restrict__ randv,
                 const void* __restrict__ hashv,
                 float* __restrict__ out,
                 int total, int pos_elems, int negs_shift, int L)
{
    if (detect_width(posv, pos_elems) != 8 || g_bad) return;  // repair covers

    const long long T = total;
    const int split = (total + 1) >> 1;
    const int base = blockIdx.x * (THREADS * EPT);

    const int* posw      = (const int*)posv;
    const long long* rnd = (const long long*)randv;
    const long long* hs  = (const long long*)hashv;

    #pragma unroll
    for (int jg = 0; jg < EPT / 2; jg++) {
        const int q = jg * THREADS + threadIdx.x;
        const int i = base + 2 * q;                     // pair (i, i+1)
        const int b = i >> negs_shift;

        const int e0 = __ldg(&posw[6 * b + 0]);
        const int r1 = __ldg(&posw[6 * b + 2]);
        const int e2 = __ldg(&posw[6 * b + 4]);

        const int4 rr = __ldg((const int4*)(rnd + i));  // (lo0,hi0,lo1,hi1)
        const int rv0 = rr.x;
        const int rv1 = rr.z;

        const bool ch0 = (i < split);
        const bool ch1 = (i + 1 < split);
        const int or0 = ch0 ? e0 : e2;
        const int or1 = ch1 ? e0 : e2;
        const int rp0 = rv0 + (((rv0 >= or0) && (or0 > 0)) ? 1 : 0);
        const int rp1 = rv1 + (((rv1 >= or1) && (or1 > 0)) ? 1 : 0);
        const int a00 = ch0 ? rp0 : e0;
        const int a20 = ch0 ? e2 : rp0;
        const int a01 = ch1 ? rp1 : e0;
        const int a21 = ch1 ? e2 : rp1;

        const unsigned int hi0 = ((unsigned int)a00 << 10) | ((unsigned int)r1 >> 11);
        const unsigned int lo0 = ((unsigned int)r1 << 21) | (unsigned int)a20;
        const unsigned int hi1 = ((unsigned int)a01 << 10) | ((unsigned int)r1 >> 11);
        const unsigned int lo1 = ((unsigned int)r1 << 21) | (unsigned int)a21;
        const long long h0 = (long long)(((unsigned long long)hi0 << 32) | lo0);
        const long long h1 = (long long)(((unsigned long long)hi1 << 32) | lo1);

        unsigned int w0, m0, w1, m1;
        bloom_wm(h0, w0, m0);
        bloom_wm(h1, w1, m1);
        const unsigned int word0 = __ldg(&g_bloom[w0]);
        const unsigned int word1 = __ldg(&g_bloom[w1]);
        const bool maybe0 = (word0 & m0) == m0;         // FP ~0.2%
        const bool maybe1 = (word1 & m1) == m1;

        bool in0 = false, in1 = false;
        if (maybe0) {
            const unsigned int bk0 = (((unsigned int)a00 << 2)
                                    | (((unsigned int)r1 >> 8) & 3u)) & (NB - 1);
            in0 = exact_member(hs, L, h0, bk0);
        }
        if (maybe1) {
            const unsigned int bk1 = (((unsigned int)a01 << 2)
                                    | (((unsigned int)r1 >> 8) & 3u)) & (NB - 1);
            in1 = exact_member(hs, L, h1, bk1);
        }

        float2* np = (float2*)(out + (long long)i * 3);
        np[0] = make_float2((float)a00, (float)r1);
        np[1] = make_float2((float)a20, (float)a01);
        np[2] = make_float2((float)r1,  (float)a21);
        *(float2*)(out + 3 * T + i) =
            make_float2(in0 ? 0.0f : 1.0f, in1 ? 0.0f : 1.0f);
    }
}

// ================ REPAIR KERNEL (generic bisect; early-exits) ================
__global__ __launch_bounds__(THREADS)
void repair_kernel(const void* __restrict__ posv,
                   const void* __restrict__ randv,
                   const void* __restrict__ hashv,
                   float* __restrict__ out,
                   int total, int pos_elems, int negs, int L,
                   long long keep_budget, int force)
{
    const int W = detect_width(posv, pos_elems);
    if (!force && W == 8 && !g_bad) return;           // fast kernel handled it

    const long long T = total;
    const int split = (total + 1) >> 1;
    const int base = blockIdx.x * (THREADS * EPT);

    for (int j = 0; j < EPT; j++) {
        int i = base + j * THREADS + threadIdx.x;
        if (i >= total) break;
        int b = i / negs;

        long long e0, r1, e2, rv;
        if (W == 8) {
            const long long* pos = (const long long*)posv;
            e0 = __ldg(&pos[(long long)b * 3 + 0]);
            r1 = __ldg(&pos[(long long)b * 3 + 1]);
            e2 = __ldg(&pos[(long long)b * 3 + 2]);
            rv = __ldg(&((const long long*)randv)[i]);
        } else {
            const int* pos = (const int*)posv;
            e0 = __ldg(&pos[b * 3 + 0]);
            r1 = __ldg(&pos[b * 3 + 1]);
            e2 = __ldg(&pos[b * 3 + 2]);
            rv = __ldg(&((const int*)randv)[i]);
        }
        bool chd = (i < split);
        long long orig = chd ? e0 : e2;
        long long repl = rv + (((rv >= orig) && (orig > 0)) ? 1LL : 0LL);
        if (chd) e0 = repl; else e2 = repl;

        long long h;
        if (W == 8) h = (e0 << 42) | (r1 << 21) | e2;
        else        h = (long long)(int)(((int)r1 << 21) | (int)e2);

        int lo = 0, hi = L;
        if (W == 8) {
            const long long* hsg = (const long long*)hashv;
            while (lo < hi) { int m = (lo + hi) >> 1;
                              if (__ldg(&hsg[m]) < h) lo = m + 1; else hi = m; }
        } else {
            const int* hsg = (const int*)hashv;
            int h32 = (int)h;
            while (lo < hi) { int m = (lo + hi) >> 1;
                              if (__ldg(&hsg[m]) < h32) lo = m + 1; else hi = m; }
        }
        bool in_set;
        if (W == 8) in_set = (lo < L) && (__ldg(&((const long long*)hashv)[lo]) == h);
        else        in_set = (lo < L) && (__ldg(&((const int*)hashv)[lo]) == (int)h);

        long long o = (long long)i * 3;
        out[o + 0] = (float)e0;
        out[o + 1] = (float)r1;
        out[o + 2] = (float)e2;
        if ((long long)i < keep_budget)
            out[3 * T + i] = in_set ? 0.0f : 1.0f;
    }
}

extern "C" void kernel_launch(void* const* d_in, const int* in_sizes, int n_in,
                              void* d_out, int out_size) {
    int idx[3]; int cnt = 0;
    for (int k = 0; k < n_in && cnt < 3; k++)
        if (in_sizes[k] > 1) idx[cnt++] = k;
    for (int a = 0; a < cnt; a++)
        for (int c = a + 1; c < cnt; c++)
            if (in_sizes[idx[c]] < in_sizes[idx[a]]) { int t = idx[a]; idx[a] = idx[c]; idx[c] = t; }

    int i_pos = idx[0], i_hash = idx[1], i_rand = idx[2];
    const void* pos    = d_in[i_pos];
    const void* hashes = d_in[i_hash];
    const void* rv     = d_in[i_rand];

    int total = in_sizes[i_rand];
    int B     = in_sizes[i_pos] / 3;
    int L     = in_sizes[i_hash];
    int negs  = (B > 0) ? total / B : 1;
    if (negs < 1) negs = 1;

    int negs_shift = -1;
    if ((negs & (negs - 1)) == 0) {
        negs_shift = 0;
        while ((1 << negs_shift) < negs) negs_shift++;
    }

    long long T = total;
    long long oe = out_size;
    long long keep_budget = (oe >= 3 * T) ? (oe - 3 * T) : 0;
    if (keep_budget > T) keep_budget = T;

    const int per_block = THREADS * EPT;
    const int grid = (total + per_block - 1) / per_block;

    // host-side structural guards for the fast path
    const bool host_ok = (negs_shift >= 1) && (keep_budget == T) &&
                         ((T & 1) == 0) && (total % per_block == 0);

    build_kernel<<<2048, THREADS>>>((const long long*)hashes, L, pos, in_sizes[i_pos]);

    if (host_ok) {
        fast_kernel<<<grid, THREADS>>>(pos, rv, hashes, (float*)d_out,
                                       total, in_sizes[i_pos], negs_shift, L);
        repair_kernel<<<grid, THREADS>>>(pos, rv, hashes, (float*)d_out,
                                         total, in_sizes[i_pos], negs, L,
                                         keep_budget, 0);
    } else {
        repair_kernel<<<grid, THREADS>>>(pos, rv, hashes, (float*)d_out,
                                         total, in_sizes[i_pos], negs, L,
                                         keep_budget, 1);
    }
}